// round 1
// baseline (speedup 1.0000x reference)
#include <cuda_runtime.h>
#include <cstdint>

#define N_NODES 20000
#define N_EDGES 320000
#define F 128
#define R 4

// ---------------- scratch (device globals; no allocation allowed) ----------------
__device__ float g_A[(size_t)R * N_NODES * F];   // per-relation accumulators (41 MB, fits L2)
__device__ float g_h[(size_t)N_NODES * F];       // layer-1 output
__device__ float g_ewn[N_EDGES];                 // normalized edge weights
__device__ int   g_mn, g_mx;                     // float-as-int min/max (weights >= 0)

// ---------------- edge-weight min/max + normalize ----------------
__global__ void k_minmax_init() {
    g_mn = 0x7f800000;   // +inf bits
    g_mx = 0;            // 0.0f bits (weights are >= 0)
}

__global__ void k_minmax(const float* __restrict__ ew) {
    int i = blockIdx.x * blockDim.x + threadIdx.x;
    float v = (i < N_EDGES) ? ew[i] : ew[0];
    float mn = v, mx = v;
    #pragma unroll
    for (int o = 16; o; o >>= 1) {
        mn = fminf(mn, __shfl_xor_sync(0xffffffffu, mn, o));
        mx = fmaxf(mx, __shfl_xor_sync(0xffffffffu, mx, o));
    }
    if ((threadIdx.x & 31) == 0) {
        atomicMin(&g_mn, __float_as_int(mn));
        atomicMax(&g_mx, __float_as_int(mx));
    }
}

__global__ void k_norm(const float* __restrict__ ew) {
    int i = blockIdx.x * blockDim.x + threadIdx.x;
    if (i >= N_EDGES) return;
    float mn = __int_as_float(g_mn);
    float mx = __int_as_float(g_mx);
    g_ewn[i] = (ew[i] - mn) * (1.0f / (mx - mn + 1e-8f));
}

// ---------------- zero the relation accumulators ----------------
__global__ void k_zero() {
    size_t i = (size_t)blockIdx.x * blockDim.x + threadIdx.x;
    size_t total = (size_t)R * N_NODES * F / 4;
    if (i < total) ((float4*)g_A)[i] = make_float4(0.f, 0.f, 0.f, 0.f);
}

// ---------------- scatter: A[r][dst] += ew * x[src], one warp per edge ----------------
__global__ void k_scatter(const float* __restrict__ x,
                          const int* __restrict__ src,
                          const int* __restrict__ dst,
                          const int* __restrict__ et,
                          int use_h) {
    int gw = (int)(((size_t)blockIdx.x * blockDim.x + threadIdx.x) >> 5);
    if (gw >= N_EDGES) return;
    int lane = threadIdx.x & 31;

    const float* xin = use_h ? g_h : x;
    int s = src[gw];
    int d = dst[gw];
    int r = et[gw];
    float w = g_ewn[gw];

    float4 xv = ((const float4*)(xin + (size_t)s * F))[lane];
    float4 v  = make_float4(xv.x * w, xv.y * w, xv.z * w, xv.w * w);

    float* outp = g_A + ((size_t)r * N_NODES + d) * F + lane * 4;
    asm volatile("red.global.add.v4.f32 [%0], {%1,%2,%3,%4};"
                 :: "l"(outp), "f"(v.x), "f"(v.y), "f"(v.z), "f"(v.w)
                 : "memory");
}

// ---------------- combine: out = relu?( [A0|A1|A2|A3|Xin] @ [W;root] + b ) ----------------
// Tiled fp32 GEMM: BM=128, BN=128, BK=32, 256 threads, 8x8 strided per thread.
// use_h selects whether the "Xin"/root segment (and the GEMM input) is g_h or the x param.
__global__ void __launch_bounds__(256, 2)
k_combine(const float* __restrict__ Xparam,  // [N,F] (layer-1 input x)
          const float* __restrict__ Wrel,    // [R,F,F]
          const float* __restrict__ root,    // [F,F]
          const float* __restrict__ bias,    // [F]
          float* __restrict__ out_param,     // final out, or nullptr -> g_h
          int do_relu, int use_h) {
    __shared__ float Xs[32][129];   // [k][row], padded: conflict-free transpose writes
    __shared__ float Ws[32][128];   // [k][col]

    float* out = out_param ? out_param : g_h;
    const float* Xin = use_h ? g_h : Xparam;

    int t  = threadIdx.x;
    int tx = t & 15;            // column group
    int ty = t >> 4;            // row group
    int row0 = blockIdx.x * 128;

    float acc[8][8];
    #pragma unroll
    for (int i = 0; i < 8; i++)
        #pragma unroll
        for (int j = 0; j < 8; j++) acc[i][j] = 0.f;

    // 5 segments of K=128: relations 0..3 from g_A, then Xin with root
    for (int seg = 0; seg < 5; seg++) {
        const float* srcp = (seg < 4) ? (g_A + (size_t)seg * N_NODES * F) : Xin;
        const float* wseg = (seg < 4) ? (Wrel + (size_t)seg * F * F)      : root;

        for (int k0 = 0; k0 < F; k0 += 32) {
            __syncthreads();
            // load X tile [128 rows x 32 k] -> Xs[k][row] (transpose)
            #pragma unroll
            for (int it = 0; it < 4; it++) {
                int idx  = t + it * 256;        // 0..1023 float4 slots
                int rrow = idx >> 3;            // 0..127
                int kq   = (idx & 7) * 4;       // 0..28
                int grow = row0 + rrow;
                float4 v = (grow < N_NODES)
                         ? ((const float4*)(srcp + (size_t)grow * F + k0 + kq))[0]
                         : make_float4(0.f, 0.f, 0.f, 0.f);
                Xs[kq + 0][rrow] = v.x;
                Xs[kq + 1][rrow] = v.y;
                Xs[kq + 2][rrow] = v.z;
                Xs[kq + 3][rrow] = v.w;
            }
            // load W tile [32 k x 128 cols] -> Ws[k][col]
            #pragma unroll
            for (int it = 0; it < 4; it++) {
                int idx  = t + it * 256;
                int krow = idx >> 5;            // 0..31
                int cq   = (idx & 31) * 4;      // 0..124
                float4 v = ((const float4*)(wseg + (size_t)(k0 + krow) * F + cq))[0];
                ((float4*)&Ws[krow][cq])[0] = v;
            }
            __syncthreads();

            #pragma unroll
            for (int kk = 0; kk < 32; kk++) {
                float a[8], b[8];
                #pragma unroll
                for (int i = 0; i < 8; i++) a[i] = Xs[kk][ty + 16 * i];
                #pragma unroll
                for (int j = 0; j < 8; j++) b[j] = Ws[kk][tx + 16 * j];
                #pragma unroll
                for (int i = 0; i < 8; i++)
                    #pragma unroll
                    for (int j = 0; j < 8; j++)
                        acc[i][j] += a[i] * b[j];
            }
        }
    }

    #pragma unroll
    for (int i = 0; i < 8; i++) {
        int grow = row0 + ty + 16 * i;
        if (grow >= N_NODES) continue;
        #pragma unroll
        for (int j = 0; j < 8; j++) {
            int col = tx + 16 * j;
            float v = acc[i][j] + bias[col];
            if (do_relu) v = fmaxf(v, 0.f);
            out[(size_t)grow * F + col] = v;
        }
    }
}

// ---------------- launcher ----------------
extern "C" void kernel_launch(void* const* d_in, const int* in_sizes, int n_in,
                              void* d_out, int out_size) {
    const float* x     = (const float*)d_in[0];
    const int*   ei    = (const int*)d_in[1];     // [2, E]
    const int*   srcp  = ei;
    const int*   dstp  = ei + N_EDGES;
    const int*   et    = (const int*)d_in[2];
    const float* ew    = (const float*)d_in[3];
    const float* W1    = (const float*)d_in[4];
    const float* root1 = (const float*)d_in[5];
    const float* b1    = (const float*)d_in[6];
    const float* W2    = (const float*)d_in[7];
    const float* root2 = (const float*)d_in[8];
    const float* b2    = (const float*)d_in[9];
    float* out = (float*)d_out;

    const int zthreads = 256;
    const int zblocks  = (int)(((size_t)R * N_NODES * F / 4 + zthreads - 1) / zthreads);
    const int eblocks  = (N_EDGES + 255) / 256;
    const int sblocks  = (int)(((size_t)N_EDGES * 32 + 255) / 256);
    const int cblocks  = (N_NODES + 127) / 128;

    // edge-weight normalization
    k_minmax_init<<<1, 1>>>();
    k_minmax<<<eblocks, 256>>>(ew);
    k_norm<<<eblocks, 256>>>(ew);

    // layer 1: A_r = scatter(ew * x[src]); h = relu([A|x] @ [W1;root1] + b1)
    k_zero<<<zblocks, zthreads>>>();
    k_scatter<<<sblocks, 256>>>(x, srcp, dstp, et, /*use_h=*/0);
    k_combine<<<cblocks, 256>>>(x, W1, root1, b1, /*out=*/nullptr, /*relu=*/1, /*use_h=*/0);

    // layer 2: A_r = scatter(ew * h[src]); out = [A|h] @ [W2;root2] + b2
    k_zero<<<zblocks, zthreads>>>();
    k_scatter<<<sblocks, 256>>>(x, srcp, dstp, et, /*use_h=*/1);
    k_combine<<<cblocks, 256>>>(x, W2, root2, b2, out, /*relu=*/0, /*use_h=*/1);
}

// round 3
// speedup vs baseline: 1.2270x; 1.2270x over previous
#include <cuda_runtime.h>
#include <cstdint>

#define N_NODES 20000
#define N_EDGES 320000
#define F 128
#define R 4
#define NBUCKETS (R * N_NODES)
#define CAP 64            // max edges per (relation,dst) bucket; Poisson(4) => P(>=64) ~ 1e-60

// ---------------- scratch (device globals; no allocation allowed) ----------------
__device__ float g_A[(size_t)R * N_NODES * F];        // per-relation aggregated messages (41 MB)
__device__ float g_h[(size_t)N_NODES * F];            // layer-1 output
__device__ int   g_cnt[NBUCKETS];                     // bucket fill counts
__device__ int2  g_slots[(size_t)NBUCKETS * CAP];     // (src, w-bits) per bucket slot
__device__ int   g_mn, g_mx;                          // float-as-int min/max (weights >= 0)

// ---------------- edge-weight min/max ----------------
__global__ void k_minmax_init() {
    g_mn = 0x7f800000;   // +inf bits
    g_mx = 0;            // 0.0f bits (weights >= 0 so int-compare works)
}

__global__ void k_minmax(const float* __restrict__ ew) {
    int i = blockIdx.x * blockDim.x + threadIdx.x;
    float v = (i < N_EDGES) ? ew[i] : ew[0];
    float mn = v, mx = v;
    #pragma unroll
    for (int o = 16; o; o >>= 1) {
        mn = fminf(mn, __shfl_xor_sync(0xffffffffu, mn, o));
        mx = fmaxf(mx, __shfl_xor_sync(0xffffffffu, mx, o));
    }
    if ((threadIdx.x & 31) == 0) {
        atomicMin(&g_mn, __float_as_int(mn));
        atomicMax(&g_mx, __float_as_int(mx));
    }
}

// ---------------- zero bucket counters ----------------
__global__ void k_zero_cnt() {
    int i = blockIdx.x * blockDim.x + threadIdx.x;
    if (i < NBUCKETS) g_cnt[i] = 0;
}

// ---------------- bucket build (once per call, shared by both layers) ----------------
__global__ void k_build(const int* __restrict__ src, const int* __restrict__ dst,
                        const int* __restrict__ et, const float* __restrict__ ew) {
    int e = blockIdx.x * blockDim.x + threadIdx.x;
    if (e >= N_EDGES) return;
    float mn = __int_as_float(g_mn);
    float mx = __int_as_float(g_mx);
    float w = (ew[e] - mn) * (1.0f / (mx - mn + 1e-8f));
    int b = et[e] * N_NODES + dst[e];
    int slot = atomicAdd(&g_cnt[b], 1);
    if (slot < CAP)
        g_slots[(size_t)b * CAP + slot] = make_int2(src[e], __float_as_int(w));
}

// ---------------- aggregate: A[b] = sum over bucket b of w * xin[src]  (no atomics) ----------
__global__ void k_agg(const float* __restrict__ x, int use_h) {
    int b = (int)(((size_t)blockIdx.x * blockDim.x + threadIdx.x) >> 5);
    if (b >= NBUCKETS) return;
    int lane = threadIdx.x & 31;
    const float* xin = use_h ? g_h : x;

    int n = g_cnt[b];
    n = n > CAP ? CAP : n;          // saturate (defensive: cnt may exceed CAP)
    const int2* sl = g_slots + (size_t)b * CAP;

    float4 acc = make_float4(0.f, 0.f, 0.f, 0.f);
    int i = 0;
    // process pairs: one int4 broadcast load covers two (src,w) entries
    for (; i + 1 < n; i += 2) {
        int4 e2 = __ldg((const int4*)&sl[i]);
        float w0 = __int_as_float(e2.y);
        float w1 = __int_as_float(e2.w);
        float4 x0 = ((const float4*)(xin + (size_t)e2.x * F))[lane];
        float4 x1 = ((const float4*)(xin + (size_t)e2.z * F))[lane];
        acc.x += w0 * x0.x + w1 * x1.x;
        acc.y += w0 * x0.y + w1 * x1.y;
        acc.z += w0 * x0.z + w1 * x1.z;
        acc.w += w0 * x0.w + w1 * x1.w;
    }
    if (i < n) {
        int2 e = __ldg(&sl[i]);
        float w = __int_as_float(e.y);
        float4 xv = ((const float4*)(xin + (size_t)e.x * F))[lane];
        acc.x += w * xv.x;
        acc.y += w * xv.y;
        acc.z += w * xv.z;
        acc.w += w * xv.w;
    }
    ((float4*)(g_A + (size_t)b * F))[lane] = acc;   // bucket b = r*N_NODES+d -> A[r][d][:]
}

// ---------------- combine: out = relu?( [A0|A1|A2|A3|Xin] @ [W;root] + b ) ----------------
// BM=128, BN=128, BK=32, 256 threads. Per-thread 8x8 as 2x(float4 rows) x 2x(float4 cols):
// fragment loads are 4x LDS.128/k-step, outputs STG.128.
__global__ void __launch_bounds__(256, 2)
k_combine(const float* __restrict__ Xparam,  // [N,F] (layer-1 input x)
          const float* __restrict__ Wrel,    // [R,F,F]
          const float* __restrict__ root,    // [F,F]
          const float* __restrict__ bias,    // [F]
          float* __restrict__ out_param,     // final out, or nullptr -> g_h
          int do_relu, int use_h) {
    __shared__ float Xs[32][132];   // [k][row], stride 132: 16B-aligned float4 reads
    __shared__ float Ws[32][132];   // [k][col]

    float* out = out_param ? out_param : g_h;
    const float* Xin = use_h ? g_h : Xparam;

    int t  = threadIdx.x;
    int tx = t & 15;            // column quad id (cols tx*4..+3 and +64)
    int ty = t >> 4;            // row quad id    (rows ty*4..+3 and +64)
    int row0 = blockIdx.x * 128;

    float acc[8][8];
    #pragma unroll
    for (int i = 0; i < 8; i++)
        #pragma unroll
        for (int j = 0; j < 8; j++) acc[i][j] = 0.f;

    // 5 segments of K=128: relations 0..3 from g_A, then Xin with root
    for (int seg = 0; seg < 5; seg++) {
        const float* srcp = (seg < 4) ? (g_A + (size_t)seg * N_NODES * F) : Xin;
        const float* wseg = (seg < 4) ? (Wrel + (size_t)seg * F * F)      : root;

        for (int k0 = 0; k0 < F; k0 += 32) {
            __syncthreads();
            // load X tile [128 rows x 32 k] -> Xs[k][row] (transpose)
            #pragma unroll
            for (int it = 0; it < 4; it++) {
                int idx  = t + it * 256;        // 0..1023 float4 slots
                int rrow = idx >> 3;            // 0..127
                int kq   = (idx & 7) * 4;       // 0..28
                int grow = row0 + rrow;
                float4 v = (grow < N_NODES)
                         ? ((const float4*)(srcp + (size_t)grow * F + k0 + kq))[0]
                         : make_float4(0.f, 0.f, 0.f, 0.f);
                Xs[kq + 0][rrow] = v.x;
                Xs[kq + 1][rrow] = v.y;
                Xs[kq + 2][rrow] = v.z;
                Xs[kq + 3][rrow] = v.w;
            }
            // load W tile [32 k x 128 cols] -> Ws[k][col]
            #pragma unroll
            for (int it = 0; it < 4; it++) {
                int idx  = t + it * 256;
                int krow = idx >> 5;            // 0..31
                int cq   = (idx & 31) * 4;      // 0..124
                float4 v = ((const float4*)(wseg + (size_t)(k0 + krow) * F + cq))[0];
                ((float4*)&Ws[krow][cq])[0] = v;
            }
            __syncthreads();

            #pragma unroll
            for (int kk = 0; kk < 32; kk++) {
                float4 a0 = *(const float4*)&Xs[kk][ty * 4];
                float4 a1 = *(const float4*)&Xs[kk][ty * 4 + 64];
                float4 b0 = *(const float4*)&Ws[kk][tx * 4];
                float4 b1 = *(const float4*)&Ws[kk][tx * 4 + 64];
                float a[8] = {a0.x, a0.y, a0.z, a0.w, a1.x, a1.y, a1.z, a1.w};
                float b[8] = {b0.x, b0.y, b0.z, b0.w, b1.x, b1.y, b1.z, b1.w};
                #pragma unroll
                for (int i = 0; i < 8; i++)
                    #pragma unroll
                    for (int j = 0; j < 8; j++)
                        acc[i][j] += a[i] * b[j];
            }
        }
    }

    // epilogue: bias (+relu), vectorized stores
    float4 bv0 = *(const float4*)&bias[tx * 4];
    float4 bv1 = *(const float4*)&bias[tx * 4 + 64];
    #pragma unroll
    for (int i = 0; i < 8; i++) {
        int grow = row0 + (i < 4 ? ty * 4 + i : 64 + ty * 4 + (i - 4));
        if (grow >= N_NODES) continue;
        float4 v0 = make_float4(acc[i][0] + bv0.x, acc[i][1] + bv0.y,
                                acc[i][2] + bv0.z, acc[i][3] + bv0.w);
        float4 v1 = make_float4(acc[i][4] + bv1.x, acc[i][5] + bv1.y,
                                acc[i][6] + bv1.z, acc[i][7] + bv1.w);
        if (do_relu) {
            v0.x = fmaxf(v0.x, 0.f); v0.y = fmaxf(v0.y, 0.f);
            v0.z = fmaxf(v0.z, 0.f); v0.w = fmaxf(v0.w, 0.f);
            v1.x = fmaxf(v1.x, 0.f); v1.y = fmaxf(v1.y, 0.f);
            v1.z = fmaxf(v1.z, 0.f); v1.w = fmaxf(v1.w, 0.f);
        }
        ((float4*)(out + (size_t)grow * F + tx * 4))[0]      = v0;
        ((float4*)(out + (size_t)grow * F + tx * 4 + 64))[0] = v1;
    }
}

// ---------------- launcher ----------------
extern "C" void kernel_launch(void* const* d_in, const int* in_sizes, int n_in,
                              void* d_out, int out_size) {
    const float* x     = (const float*)d_in[0];
    const int*   ei    = (const int*)d_in[1];     // [2, E]
    const int*   srcp  = ei;
    const int*   dstp  = ei + N_EDGES;
    const int*   et    = (const int*)d_in[2];
    const float* ew    = (const float*)d_in[3];
    const float* W1    = (const float*)d_in[4];
    const float* root1 = (const float*)d_in[5];
    const float* b1    = (const float*)d_in[6];
    const float* W2    = (const float*)d_in[7];
    const float* root2 = (const float*)d_in[8];
    const float* b2    = (const float*)d_in[9];
    float* out = (float*)d_out;

    const int eblocks = (N_EDGES + 255) / 256;
    const int cblocks = (N_NODES + 127) / 128;
    const int ablocks = (NBUCKETS * 32 + 255) / 256;   // one warp per bucket
    const int zblocks = (NBUCKETS + 255) / 256;

    // edge-weight normalization prep + bucket build (shared by both layers)
    k_minmax_init<<<1, 1>>>();
    k_zero_cnt<<<zblocks, 256>>>();
    k_minmax<<<eblocks, 256>>>(ew);
    k_build<<<eblocks, 256>>>(srcp, dstp, et, ew);

    // layer 1: A = gather-aggregate(x); h = relu([A|x] @ [W1;root1] + b1)
    k_agg<<<ablocks, 256>>>(x, /*use_h=*/0);
    k_combine<<<cblocks, 256>>>(x, W1, root1, b1, /*out=*/nullptr, /*relu=*/1, /*use_h=*/0);

    // layer 2: A = gather-aggregate(h); out = [A|h] @ [W2;root2] + b2
    k_agg<<<ablocks, 256>>>(x, /*use_h=*/1);
    k_combine<<<cblocks, 256>>>(x, W2, root2, b2, out, /*relu=*/0, /*use_h=*/1);
}

// round 4
// speedup vs baseline: 2.4821x; 2.0229x over previous
#include <cuda_runtime.h>
#include <cstdint>

#define N_NODES 20000
#define N_EDGES 320000
#define F 128
#define R 4
#define NBUCKETS (R * N_NODES)
#define CAP 64            // max edges per (relation,dst) bucket; Poisson(4) => P(>=64) ~ 1e-60

// ---------------- scratch (device globals; no allocation allowed) ----------------
__device__ float g_A[(size_t)R * N_NODES * F];        // per-relation aggregated messages (41 MB)
__device__ float g_h[(size_t)N_NODES * F];            // layer-1 output
__device__ int   g_cnt[NBUCKETS];                     // bucket fill counts
__device__ int2  g_slots[(size_t)NBUCKETS * CAP];     // (src, w-bits) per bucket slot
__device__ int   g_mn, g_mx;                          // float-as-int min/max (weights >= 0)

// ---------------- edge-weight min/max ----------------
__global__ void k_minmax_init() {
    g_mn = 0x7f800000;   // +inf bits
    g_mx = 0;            // 0.0f bits (weights >= 0 so int-compare works)
}

__global__ void k_minmax(const float* __restrict__ ew) {
    int i = blockIdx.x * blockDim.x + threadIdx.x;
    float v = (i < N_EDGES) ? ew[i] : ew[0];
    float mn = v, mx = v;
    #pragma unroll
    for (int o = 16; o; o >>= 1) {
        mn = fminf(mn, __shfl_xor_sync(0xffffffffu, mn, o));
        mx = fmaxf(mx, __shfl_xor_sync(0xffffffffu, mx, o));
    }
    if ((threadIdx.x & 31) == 0) {
        atomicMin(&g_mn, __float_as_int(mn));
        atomicMax(&g_mx, __float_as_int(mx));
    }
}

// ---------------- zero bucket counters ----------------
__global__ void k_zero_cnt() {
    int i = blockIdx.x * blockDim.x + threadIdx.x;
    if (i < NBUCKETS) g_cnt[i] = 0;
}

// ---------------- bucket build (once per call, shared by both layers) ----------------
__global__ void k_build(const int* __restrict__ src, const int* __restrict__ dst,
                        const int* __restrict__ et, const float* __restrict__ ew) {
    int e = blockIdx.x * blockDim.x + threadIdx.x;
    if (e >= N_EDGES) return;
    float mn = __int_as_float(g_mn);
    float mx = __int_as_float(g_mx);
    float w = (ew[e] - mn) * (1.0f / (mx - mn + 1e-8f));
    int b = et[e] * N_NODES + dst[e];
    int slot = atomicAdd(&g_cnt[b], 1);
    if (slot < CAP)
        g_slots[(size_t)b * CAP + slot] = make_int2(src[e], __float_as_int(w));
}

// ---------------- aggregate: A[b] = sum over bucket b of w * xin[src]  (no atomics) ----------
__global__ void k_agg(const float* __restrict__ x, int use_h) {
    int b = (int)(((size_t)blockIdx.x * blockDim.x + threadIdx.x) >> 5);
    if (b >= NBUCKETS) return;
    int lane = threadIdx.x & 31;
    const float* xin = use_h ? g_h : x;

    int n = g_cnt[b];
    n = n > CAP ? CAP : n;          // saturate (defensive)
    const int2* sl = g_slots + (size_t)b * CAP;

    float4 acc = make_float4(0.f, 0.f, 0.f, 0.f);
    int i = 0;
    for (; i + 1 < n; i += 2) {
        int4 e2 = __ldg((const int4*)&sl[i]);
        float w0 = __int_as_float(e2.y);
        float w1 = __int_as_float(e2.w);
        float4 x0 = ((const float4*)(xin + (size_t)e2.x * F))[lane];
        float4 x1 = ((const float4*)(xin + (size_t)e2.z * F))[lane];
        acc.x += w0 * x0.x + w1 * x1.x;
        acc.y += w0 * x0.y + w1 * x1.y;
        acc.z += w0 * x0.z + w1 * x1.z;
        acc.w += w0 * x0.w + w1 * x1.w;
    }
    if (i < n) {
        int2 e = __ldg(&sl[i]);
        float w = __int_as_float(e.y);
        float4 xv = ((const float4*)(xin + (size_t)e.x * F))[lane];
        acc.x += w * xv.x;
        acc.y += w * xv.y;
        acc.z += w * xv.z;
        acc.w += w * xv.w;
    }
    ((float4*)(g_A + (size_t)b * F))[lane] = acc;
}

// ---------------- tf32 helpers ----------------
__device__ __forceinline__ uint32_t f2tf32(float f) {
    uint32_t r;
    asm("cvt.rna.tf32.f32 %0, %1;" : "=r"(r) : "f"(f));
    return r;
}

#define MMA_TF32(d, a0, a1, a2, a3, b0, b1)                                   \
    asm volatile("mma.sync.aligned.m16n8k8.row.col.f32.tf32.tf32.f32 "        \
                 "{%0,%1,%2,%3}, {%4,%5,%6,%7}, {%8,%9}, {%0,%1,%2,%3};"      \
                 : "+f"((d)[0]), "+f"((d)[1]), "+f"((d)[2]), "+f"((d)[3])     \
                 : "r"(a0), "r"(a1), "r"(a2), "r"(a3), "r"(b0), "r"(b1))

// ---------------- combine: out = relu?( [A0|A1|A2|A3|Xin] @ [W;root] + b ) ----------------
// tf32 tensor-core GEMM. BM=128, BN=128, BK=32, 256 threads = 8 warps (4x2),
// warp tile 32x64 = 2 m16-tiles x 8 n8-tiles, mma.sync.m16n8k8.
__global__ void __launch_bounds__(256, 2)
k_combine(const float* __restrict__ Xparam,  // [N,F] (layer-1 input x)
          const float* __restrict__ Wrel,    // [R,F,F]
          const float* __restrict__ root,    // [F,F]
          const float* __restrict__ bias,    // [F]
          float* __restrict__ out_param,     // final out, or nullptr -> g_h
          int do_relu, int use_h) {
    __shared__ uint32_t Xs[128][36];   // tf32 A tile, row-major; pad 36: conflict-free frags
    __shared__ uint32_t Ws[32][136];   // tf32 B tile [k][col];  pad 136: conflict-free frags

    float* out = out_param ? out_param : g_h;
    const float* Xin = use_h ? g_h : Xparam;

    int t    = threadIdx.x;
    int lane = t & 31;
    int w    = t >> 5;          // warp 0..7
    int wm   = w & 3;           // row group: rows wm*32..+31
    int wn   = w >> 2;          // col group: cols wn*64..+63
    int gid  = lane >> 2;       // 0..7
    int tid4 = lane & 3;        // 0..3
    int row0 = blockIdx.x * 128;

    float acc[2][8][4];
    #pragma unroll
    for (int mt = 0; mt < 2; mt++)
        #pragma unroll
        for (int nt = 0; nt < 8; nt++)
            #pragma unroll
            for (int q = 0; q < 4; q++) acc[mt][nt][q] = 0.f;

    // 5 K-segments of 128: relations 0..3 from g_A, then Xin with root
    for (int seg = 0; seg < 5; seg++) {
        const float* srcp = (seg < 4) ? (g_A + (size_t)seg * N_NODES * F) : Xin;
        const float* wseg = (seg < 4) ? (Wrel + (size_t)seg * F * F)      : root;

        for (int k0 = 0; k0 < F; k0 += 32) {
            __syncthreads();
            // X tile [128 rows x 32 k] -> Xs[row][k], converted to tf32
            #pragma unroll
            for (int it = 0; it < 4; it++) {
                int idx  = t + it * 256;        // 0..1023 float4 slots
                int rrow = idx >> 3;            // 0..127
                int kq   = (idx & 7) * 4;       // 0..28
                int grow = row0 + rrow;
                float4 v = (grow < N_NODES)
                         ? ((const float4*)(srcp + (size_t)grow * F + k0 + kq))[0]
                         : make_float4(0.f, 0.f, 0.f, 0.f);
                uint4 u = make_uint4(f2tf32(v.x), f2tf32(v.y), f2tf32(v.z), f2tf32(v.w));
                *(uint4*)&Xs[rrow][kq] = u;
            }
            // W tile [32 k x 128 cols] -> Ws[k][col], converted to tf32
            #pragma unroll
            for (int it = 0; it < 4; it++) {
                int idx  = t + it * 256;
                int krow = idx >> 5;            // 0..31
                int cq   = (idx & 31) * 4;      // 0..124
                float4 v = ((const float4*)(wseg + (size_t)(k0 + krow) * F + cq))[0];
                uint4 u = make_uint4(f2tf32(v.x), f2tf32(v.y), f2tf32(v.z), f2tf32(v.w));
                *(uint4*)&Ws[krow][cq] = u;
            }
            __syncthreads();

            #pragma unroll
            for (int kk = 0; kk < 32; kk += 8) {
                uint32_t a[2][4];
                #pragma unroll
                for (int mt = 0; mt < 2; mt++) {
                    int row = wm * 32 + mt * 16 + gid;
                    a[mt][0] = Xs[row][kk + tid4];
                    a[mt][1] = Xs[row + 8][kk + tid4];
                    a[mt][2] = Xs[row][kk + tid4 + 4];
                    a[mt][3] = Xs[row + 8][kk + tid4 + 4];
                }
                #pragma unroll
                for (int nt = 0; nt < 8; nt++) {
                    int col = wn * 64 + nt * 8 + gid;
                    uint32_t b0 = Ws[kk + tid4][col];
                    uint32_t b1 = Ws[kk + tid4 + 4][col];
                    MMA_TF32(acc[0][nt], a[0][0], a[0][1], a[0][2], a[0][3], b0, b1);
                    MMA_TF32(acc[1][nt], a[1][0], a[1][1], a[1][2], a[1][3], b0, b1);
                }
            }
        }
    }

    // epilogue: c-frag layout: rows base+gid / base+gid+8, cols colb + tid4*2, +1
    #pragma unroll
    for (int mt = 0; mt < 2; mt++) {
        int rbase = row0 + wm * 32 + mt * 16 + gid;
        #pragma unroll
        for (int half = 0; half < 2; half++) {
            int grow = rbase + half * 8;
            if (grow >= N_NODES) continue;
            #pragma unroll
            for (int nt = 0; nt < 8; nt++) {
                int col = wn * 64 + nt * 8 + tid4 * 2;
                float v0 = acc[mt][nt][half * 2 + 0] + __ldg(&bias[col]);
                float v1 = acc[mt][nt][half * 2 + 1] + __ldg(&bias[col + 1]);
                if (do_relu) { v0 = fmaxf(v0, 0.f); v1 = fmaxf(v1, 0.f); }
                *(float2*)(out + (size_t)grow * F + col) = make_float2(v0, v1);
            }
        }
    }
}

// ---------------- launcher ----------------
extern "C" void kernel_launch(void* const* d_in, const int* in_sizes, int n_in,
                              void* d_out, int out_size) {
    const float* x     = (const float*)d_in[0];
    const int*   ei    = (const int*)d_in[1];     // [2, E]
    const int*   srcp  = ei;
    const int*   dstp  = ei + N_EDGES;
    const int*   et    = (const int*)d_in[2];
    const float* ew    = (const float*)d_in[3];
    const float* W1    = (const float*)d_in[4];
    const float* root1 = (const float*)d_in[5];
    const float* b1    = (const float*)d_in[6];
    const float* W2    = (const float*)d_in[7];
    const float* root2 = (const float*)d_in[8];
    const float* b2    = (const float*)d_in[9];
    float* out = (float*)d_out;

    const int eblocks = (N_EDGES + 255) / 256;
    const int cblocks = (N_NODES + 127) / 128;
    const int ablocks = (NBUCKETS * 32 + 255) / 256;   // one warp per bucket
    const int zblocks = (NBUCKETS + 255) / 256;

    // edge-weight normalization prep + bucket build (shared by both layers)
    k_minmax_init<<<1, 1>>>();
    k_zero_cnt<<<zblocks, 256>>>();
    k_minmax<<<eblocks, 256>>>(ew);
    k_build<<<eblocks, 256>>>(srcp, dstp, et, ew);

    // layer 1: A = gather-aggregate(x); h = relu([A|x] @ [W1;root1] + b1)
    k_agg<<<ablocks, 256>>>(x, /*use_h=*/0);
    k_combine<<<cblocks, 256>>>(x, W1, root1, b1, /*out=*/nullptr, /*relu=*/1, /*use_h=*/0);

    // layer 2: A = gather-aggregate(h); out = [A|h] @ [W2;root2] + b2
    k_agg<<<ablocks, 256>>>(x, /*use_h=*/1);
    k_combine<<<cblocks, 256>>>(x, W2, root2, b2, out, /*relu=*/0, /*use_h=*/1);
}

// round 6
// speedup vs baseline: 2.7033x; 1.0891x over previous
#include <cuda_runtime.h>
#include <cstdint>

#define N_NODES 20000
#define N_EDGES 320000
#define F 128
#define R 4
#define NBUCKETS (R * N_NODES)
#define CAP 64            // max edges per (relation,dst) bucket; Poisson(4) => P(>=64) ~ 1e-60

// ---------------- scratch (device globals; no allocation allowed) ----------------
__device__ float g_A[(size_t)R * N_NODES * F];        // per-relation aggregated messages (41 MB)
__device__ float g_h[(size_t)N_NODES * F];            // layer-1 output
__device__ int   g_cnt[NBUCKETS];                     // bucket fill counts
__device__ int2  g_slots[(size_t)NBUCKETS * CAP];     // (src, w-bits) per bucket slot
__device__ int   g_mn, g_mx;                          // float-as-int min/max (weights >= 0)

// ---------------- init: minmax seeds + zero bucket counters (one launch) ----------------
__global__ void k_init() {
    int i = blockIdx.x * blockDim.x + threadIdx.x;
    if (i == 0) {
        g_mn = 0x7f800000;   // +inf bits
        g_mx = 0;            // 0.0f bits (weights >= 0 so int-compare works)
    }
    if (i < NBUCKETS) g_cnt[i] = 0;
}

__global__ void k_minmax(const float* __restrict__ ew) {
    int i = blockIdx.x * blockDim.x + threadIdx.x;
    float v = (i < N_EDGES) ? ew[i] : ew[0];
    float mn = v, mx = v;
    #pragma unroll
    for (int o = 16; o; o >>= 1) {
        mn = fminf(mn, __shfl_xor_sync(0xffffffffu, mn, o));
        mx = fmaxf(mx, __shfl_xor_sync(0xffffffffu, mx, o));
    }
    if ((threadIdx.x & 31) == 0) {
        atomicMin(&g_mn, __float_as_int(mn));
        atomicMax(&g_mx, __float_as_int(mx));
    }
}

// ---------------- bucket build (once per call, shared by both layers); 2 edges/thread ------
__global__ void k_build(const int* __restrict__ src, const int* __restrict__ dst,
                        const int* __restrict__ et, const float* __restrict__ ew) {
    int base = (blockIdx.x * blockDim.x + threadIdx.x) * 2;
    float mn = __int_as_float(g_mn);
    float mx = __int_as_float(g_mx);
    float inv = 1.0f / (mx - mn + 1e-8f);
    #pragma unroll
    for (int j = 0; j < 2; j++) {
        int e = base + j;
        if (e >= N_EDGES) break;
        float w = (ew[e] - mn) * inv;
        int b = et[e] * N_NODES + dst[e];
        int slot = atomicAdd(&g_cnt[b], 1);
        if (slot < CAP)
            g_slots[(size_t)b * CAP + slot] = make_int2(src[e], __float_as_int(w));
    }
}

// ---------------- aggregate: A[b] = sum over bucket b of w * xin[src]  (no atomics) ----------
// One warp per bucket; chunks of 4 edges with predicated weights -> MLP 4 on row gathers,
// no serial remainder loop (avg n=4 completes in one chunk). Slot reads i..i+3 stay within
// the CAP region for all i < n <= CAP.
__global__ void k_agg(const float* __restrict__ x, int use_h) {
    int b = (int)(((size_t)blockIdx.x * blockDim.x + threadIdx.x) >> 5);
    if (b >= NBUCKETS) return;
    int lane = threadIdx.x & 31;
    const float* xin = use_h ? g_h : x;

    int n = g_cnt[b];
    n = n > CAP ? CAP : n;          // saturate (defensive)
    const int2* sl = g_slots + (size_t)b * CAP;

    float4 acc = make_float4(0.f, 0.f, 0.f, 0.f);
    for (int i = 0; i < n; i += 4) {
        int4 ea = __ldg((const int4*)&sl[i]);
        int4 eb = __ldg((const int4*)&sl[i + 2]);
        // predicate: edges beyond n get weight 0 and a clamped (safe) src index
        float w0 = (i + 0 < n) ? __int_as_float(ea.y) : 0.f;
        float w1 = (i + 1 < n) ? __int_as_float(ea.w) : 0.f;
        float w2 = (i + 2 < n) ? __int_as_float(eb.y) : 0.f;
        float w3 = (i + 3 < n) ? __int_as_float(eb.w) : 0.f;
        unsigned s0 = min((unsigned)ea.x, (unsigned)(N_NODES - 1));
        unsigned s1 = min((unsigned)ea.z, (unsigned)(N_NODES - 1));
        unsigned s2 = min((unsigned)eb.x, (unsigned)(N_NODES - 1));
        unsigned s3 = min((unsigned)eb.z, (unsigned)(N_NODES - 1));
        // 4 independent 512B row gathers
        float4 x0 = ((const float4*)(xin + (size_t)s0 * F))[lane];
        float4 x1 = ((const float4*)(xin + (size_t)s1 * F))[lane];
        float4 x2 = ((const float4*)(xin + (size_t)s2 * F))[lane];
        float4 x3 = ((const float4*)(xin + (size_t)s3 * F))[lane];
        acc.x += w0 * x0.x + w1 * x1.x + w2 * x2.x + w3 * x3.x;
        acc.y += w0 * x0.y + w1 * x1.y + w2 * x2.y + w3 * x3.y;
        acc.z += w0 * x0.z + w1 * x1.z + w2 * x2.z + w3 * x3.z;
        acc.w += w0 * x0.w + w1 * x1.w + w2 * x2.w + w3 * x3.w;
    }
    ((float4*)(g_A + (size_t)b * F))[lane] = acc;
}

// ---------------- tf32 helpers ----------------
__device__ __forceinline__ uint32_t f2tf32(float f) {
    uint32_t r;
    asm("cvt.rna.tf32.f32 %0, %1;" : "=r"(r) : "f"(f));
    return r;
}

#define MMA_TF32(d, a0, a1, a2, a3, b0, b1)                                   \
    asm volatile("mma.sync.aligned.m16n8k8.row.col.f32.tf32.tf32.f32 "        \
                 "{%0,%1,%2,%3}, {%4,%5,%6,%7}, {%8,%9}, {%0,%1,%2,%3};"      \
                 : "+f"((d)[0]), "+f"((d)[1]), "+f"((d)[2]), "+f"((d)[3])     \
                 : "r"(a0), "r"(a1), "r"(a2), "r"(a3), "r"(b0), "r"(b1))

// ---------------- combine: out = relu?( [A0|A1|A2|A3|Xin] @ [W;root] + b ) ----------------
// tf32 tensor-core GEMM. BM=128, BN=128, BK=32, 256 threads = 8 warps (4x2),
// warp tile 32x64 = 2 m16-tiles x 8 n8-tiles, mma.sync.m16n8k8.
__global__ void __launch_bounds__(256, 2)
k_combine(const float* __restrict__ Xparam,  // [N,F] (layer-1 input x)
          const float* __restrict__ Wrel,    // [R,F,F]
          const float* __restrict__ root,    // [F,F]
          const float* __restrict__ bias,    // [F]
          float* __restrict__ out_param,     // final out, or nullptr -> g_h
          int do_relu, int use_h) {
    __shared__ uint32_t Xs[128][36];   // tf32 A tile, row-major; pad 36: conflict-free frags
    __shared__ uint32_t Ws[32][136];   // tf32 B tile [k][col];  pad 136: conflict-free frags

    float* out = out_param ? out_param : g_h;
    const float* Xin = use_h ? g_h : Xparam;

    int t    = threadIdx.x;
    int lane = t & 31;
    int w    = t >> 5;          // warp 0..7
    int wm   = w & 3;           // row group: rows wm*32..+31
    int wn   = w >> 2;          // col group: cols wn*64..+63
    int gid  = lane >> 2;       // 0..7
    int tid4 = lane & 3;        // 0..3
    int row0 = blockIdx.x * 128;

    float acc[2][8][4];
    #pragma unroll
    for (int mt = 0; mt < 2; mt++)
        #pragma unroll
        for (int nt = 0; nt < 8; nt++)
            #pragma unroll
            for (int q = 0; q < 4; q++) acc[mt][nt][q] = 0.f;

    // 5 K-segments of 128: relations 0..3 from g_A, then Xin with root
    for (int seg = 0; seg < 5; seg++) {
        const float* srcp = (seg < 4) ? (g_A + (size_t)seg * N_NODES * F) : Xin;
        const float* wseg = (seg < 4) ? (Wrel + (size_t)seg * F * F)      : root;

        for (int k0 = 0; k0 < F; k0 += 32) {
            __syncthreads();
            // X tile [128 rows x 32 k] -> Xs[row][k], converted to tf32
            #pragma unroll
            for (int it = 0; it < 4; it++) {
                int idx  = t + it * 256;        // 0..1023 float4 slots
                int rrow = idx >> 3;            // 0..127
                int kq   = (idx & 7) * 4;       // 0..28
                int grow = row0 + rrow;
                float4 v = (grow < N_NODES)
                         ? ((const float4*)(srcp + (size_t)grow * F + k0 + kq))[0]
                         : make_float4(0.f, 0.f, 0.f, 0.f);
                uint4 u = make_uint4(f2tf32(v.x), f2tf32(v.y), f2tf32(v.z), f2tf32(v.w));
                *(uint4*)&Xs[rrow][kq] = u;
            }
            // W tile [32 k x 128 cols] -> Ws[k][col], converted to tf32
            #pragma unroll
            for (int it = 0; it < 4; it++) {
                int idx  = t + it * 256;
                int krow = idx >> 5;            // 0..31
                int cq   = (idx & 31) * 4;      // 0..124
                float4 v = ((const float4*)(wseg + (size_t)(k0 + krow) * F + cq))[0];
                uint4 u = make_uint4(f2tf32(v.x), f2tf32(v.y), f2tf32(v.z), f2tf32(v.w));
                *(uint4*)&Ws[krow][cq] = u;
            }
            __syncthreads();

            #pragma unroll
            for (int kk = 0; kk < 32; kk += 8) {
                uint32_t a[2][4];
                #pragma unroll
                for (int mt = 0; mt < 2; mt++) {
                    int row = wm * 32 + mt * 16 + gid;
                    a[mt][0] = Xs[row][kk + tid4];
                    a[mt][1] = Xs[row + 8][kk + tid4];
                    a[mt][2] = Xs[row][kk + tid4 + 4];
                    a[mt][3] = Xs[row + 8][kk + tid4 + 4];
                }
                #pragma unroll
                for (int nt = 0; nt < 8; nt++) {
                    int col = wn * 64 + nt * 8 + gid;
                    uint32_t b0 = Ws[kk + tid4][col];
                    uint32_t b1 = Ws[kk + tid4 + 4][col];
                    MMA_TF32(acc[0][nt], a[0][0], a[0][1], a[0][2], a[0][3], b0, b1);
                    MMA_TF32(acc[1][nt], a[1][0], a[1][1], a[1][2], a[1][3], b0, b1);
                }
            }
        }
    }

    // epilogue: c-frag layout: rows base+gid / base+gid+8, cols colb + tid4*2, +1
    #pragma unroll
    for (int mt = 0; mt < 2; mt++) {
        int rbase = row0 + wm * 32 + mt * 16 + gid;
        #pragma unroll
        for (int half = 0; half < 2; half++) {
            int grow = rbase + half * 8;
            if (grow >= N_NODES) continue;
            #pragma unroll
            for (int nt = 0; nt < 8; nt++) {
                int col = wn * 64 + nt * 8 + tid4 * 2;
                float v0 = acc[mt][nt][half * 2 + 0] + __ldg(&bias[col]);
                float v1 = acc[mt][nt][half * 2 + 1] + __ldg(&bias[col + 1]);
                if (do_relu) { v0 = fmaxf(v0, 0.f); v1 = fmaxf(v1, 0.f); }
                *(float2*)(out + (size_t)grow * F + col) = make_float2(v0, v1);
            }
        }
    }
}

// ---------------- launcher ----------------
extern "C" void kernel_launch(void* const* d_in, const int* in_sizes, int n_in,
                              void* d_out, int out_size) {
    const float* x     = (const float*)d_in[0];
    const int*   ei    = (const int*)d_in[1];     // [2, E]
    const int*   srcp  = ei;
    const int*   dstp  = ei + N_EDGES;
    const int*   et    = (const int*)d_in[2];
    const float* ew    = (const float*)d_in[3];
    const float* W1    = (const float*)d_in[4];
    const float* root1 = (const float*)d_in[5];
    const float* b1    = (const float*)d_in[6];
    const float* W2    = (const float*)d_in[7];
    const float* root2 = (const float*)d_in[8];
    const float* b2    = (const float*)d_in[9];
    float* out = (float*)d_out;

    const int eblocks  = (N_EDGES + 255) / 256;
    const int bblocks  = (N_EDGES / 2 + 255) / 256;
    const int cblocks  = (N_NODES + 127) / 128;
    const int ablocks  = (NBUCKETS * 32 + 255) / 256;   // one warp per bucket
    const int iblocks  = (NBUCKETS + 255) / 256;

    // init (minmax seeds + counter zeroing), minmax, bucket build (shared by both layers)
    k_init<<<iblocks, 256>>>();
    k_minmax<<<eblocks, 256>>>(ew);
    k_build<<<bblocks, 256>>>(srcp, dstp, et, ew);

    // layer 1: A = gather-aggregate(x); h = relu([A|x] @ [W1;root1] + b1)
    k_agg<<<ablocks, 256>>>(x, /*use_h=*/0);
    k_combine<<<cblocks, 256>>>(x, W1, root1, b1, /*out=*/nullptr, /*relu=*/1, /*use_h=*/0);

    // layer 2: A = gather-aggregate(h); out = [A|h] @ [W2;root2] + b2
    k_agg<<<ablocks, 256>>>(x, /*use_h=*/1);
    k_combine<<<cblocks, 256>>>(x, W2, root2, b2, out, /*relu=*/0, /*use_h=*/1);
}